// round 4
// baseline (speedup 1.0000x reference)
#include <cuda_runtime.h>

// CPPN: [P,12] -> 32 -> 32 -> 32 -> 3, per-node activations, tanh output.
// R4: 2 pixels/thread to halve weight-LDS per pixel (L1 was 73% = bottleneck),
// k-outer loop with f32-at-rest hidden state + 16 f32x2 accumulator pairs per
// pixel, __launch_bounds__(128,1) to eliminate the register spills seen at
// regs=96. FFMA2 (fma.rn.f32x2) remains the math workhorse.

typedef unsigned long long ull;

__device__ __forceinline__ ull pk2(float lo, float hi) {
    ull r; asm("mov.b64 %0, {%1, %2};" : "=l"(r) : "f"(lo), "f"(hi)); return r;
}
__device__ __forceinline__ ull dup2(float x) { return pk2(x, x); }
__device__ __forceinline__ ull ffma2(ull a, ull b, ull c) {
    ull d; asm("fma.rn.f32x2 %0, %1, %2, %3;" : "=l"(d) : "l"(a), "l"(b), "l"(c)); return d;
}
__device__ __forceinline__ void unpk2(ull v, float& lo, float& hi) {
    asm("mov.b64 {%0, %1}, %2;" : "=f"(lo), "=f"(hi) : "l"(v));
}

// Overflow-safe fast tanh: tanh(x) = sign(x)*(1-e)/(1+e), e = exp(-2|x|) <= 1
__device__ __forceinline__ float fast_tanh(float x) {
    float ax = fabsf(x);
    float e  = __expf(-2.0f * ax);
    float t  = __fdividef(1.0f - e, 1.0f + e);
    return copysignf(t, x);
}

// 0=identity, 1=tanh, 2=sigmoid, 3=sin, 4=gaussian
__device__ __forceinline__ float actf(float x, int id) {
    switch (id) {
        case 1:  return fast_tanh(x);
        case 2:  return __fdividef(1.0f, 1.0f + __expf(-x));
        case 3:  return __sinf(x);
        case 4:  return __expf(-0.5f * x * x);
        default: return x;
    }
}

// One hidden layer for TWO pixels. h in/out are plain f32[32] per pixel.
// k-outer: one LDS.128 weight quad feeds 4 FFMA2 (2 output-pairs x 2 pixels).
template <int K>
__device__ __forceinline__ void layer2(const float* __restrict__ h0,
                                       const float* __restrict__ h1,
                                       float* __restrict__ o0,
                                       float* __restrict__ o1,
                                       const float* __restrict__ sW,
                                       const float* __restrict__ sb,
                                       const int* __restrict__ sact) {
    ull acc0[16], acc1[16];
#pragma unroll
    for (int j2 = 0; j2 < 16; j2++) {
        ull binit = pk2(sb[2 * j2], sb[2 * j2 + 1]);
        acc0[j2] = binit;
        acc1[j2] = binit;
    }
#pragma unroll
    for (int k = 0; k < K; k++) {
        ull ha = dup2(h0[k]);
        ull hb = dup2(h1[k]);
#pragma unroll
        for (int jq = 0; jq < 8; jq++) {
            float4 w = *(const float4*)(sW + k * 32 + 4 * jq);
            ull w01 = pk2(w.x, w.y);
            ull w23 = pk2(w.z, w.w);
            acc0[2 * jq + 0] = ffma2(ha, w01, acc0[2 * jq + 0]);
            acc0[2 * jq + 1] = ffma2(ha, w23, acc0[2 * jq + 1]);
            acc1[2 * jq + 0] = ffma2(hb, w01, acc1[2 * jq + 0]);
            acc1[2 * jq + 1] = ffma2(hb, w23, acc1[2 * jq + 1]);
        }
    }
#pragma unroll
    for (int j2 = 0; j2 < 16; j2++) {
        int id0 = sact[2 * j2], id1 = sact[2 * j2 + 1];
        float x0, x1;
        unpk2(acc0[j2], x0, x1);
        o0[2 * j2 + 0] = actf(x0, id0);
        o0[2 * j2 + 1] = actf(x1, id1);
        unpk2(acc1[j2], x0, x1);
        o1[2 * j2 + 0] = actf(x0, id0);
        o1[2 * j2 + 1] = actf(x1, id1);
    }
}

__global__ __launch_bounds__(128, 1) void cppn_kernel(
    const float* __restrict__ inp,       // [P,12]
    const float* __restrict__ bias_in,   // [12]
    const float* __restrict__ W1,        // [12,32]
    const float* __restrict__ b1,        // [32]
    const int*   __restrict__ a1,        // [32]
    const float* __restrict__ W2,        // [32,32]
    const float* __restrict__ b2,
    const int*   __restrict__ a2,
    const float* __restrict__ W3,        // [32,32]
    const float* __restrict__ b3,
    const int*   __restrict__ a3,
    const float* __restrict__ Wo,        // [32,3]
    const float* __restrict__ bo,        // [3]
    float* __restrict__ out,             // [P,3]
    int P)
{
    __shared__ __align__(16) float sW1[12 * 32];
    __shared__ __align__(16) float sW2[32 * 32];
    __shared__ __align__(16) float sW3[32 * 32];
    __shared__ float sWo[96];
    __shared__ float sb1[32], sb2[32], sb3[32], sbo[3], sbin[12];
    __shared__ int   sa1[32], sa2[32], sa3[32];

    const int t = threadIdx.x;
    for (int i = t; i < 12 * 32; i += 128) sW1[i] = W1[i];
    for (int i = t; i < 1024; i += 128) { sW2[i] = W2[i]; sW3[i] = W3[i]; }
    if (t < 96) sWo[t] = Wo[t];
    if (t < 32) {
        sb1[t] = b1[t]; sb2[t] = b2[t]; sb3[t] = b3[t];
        sa1[t] = a1[t]; sa2[t] = a2[t]; sa3[t] = a3[t];
    }
    if (t < 12) sbin[t] = bias_in[t];
    if (t < 3)  sbo[t]  = bo[t];
    __syncthreads();

    const int p0 = blockIdx.x * 256 + t;
    const int p1 = p0 + 128;
    if (p0 >= P) return;
    const bool has1 = (p1 < P);

    // Load 12 inputs per pixel as 3x float4 (rows are 48B, 16B-aligned)
    const float4* in4 = (const float4*)inp;
    float hA0[32], hA1[32], hB0[32], hB1[32];
    {
        float4 A = in4[3 * p0 + 0], B = in4[3 * p0 + 1], C = in4[3 * p0 + 2];
        hA0[0]  = A.x + sbin[0];  hA0[1]  = A.y + sbin[1];
        hA0[2]  = A.z + sbin[2];  hA0[3]  = A.w + sbin[3];
        hA0[4]  = B.x + sbin[4];  hA0[5]  = B.y + sbin[5];
        hA0[6]  = B.z + sbin[6];  hA0[7]  = B.w + sbin[7];
        hA0[8]  = C.x + sbin[8];  hA0[9]  = C.y + sbin[9];
        hA0[10] = C.z + sbin[10]; hA0[11] = C.w + sbin[11];
    }
    {
        int q = has1 ? p1 : p0;   // dummy-read p0 again if tail (result discarded)
        float4 A = in4[3 * q + 0], B = in4[3 * q + 1], C = in4[3 * q + 2];
        hA1[0]  = A.x + sbin[0];  hA1[1]  = A.y + sbin[1];
        hA1[2]  = A.z + sbin[2];  hA1[3]  = A.w + sbin[3];
        hA1[4]  = B.x + sbin[4];  hA1[5]  = B.y + sbin[5];
        hA1[6]  = B.z + sbin[6];  hA1[7]  = B.w + sbin[7];
        hA1[8]  = C.x + sbin[8];  hA1[9]  = C.y + sbin[9];
        hA1[10] = C.z + sbin[10]; hA1[11] = C.w + sbin[11];
    }

    layer2<12>(hA0, hA1, hB0, hB1, sW1, sb1, sa1);
    layer2<32>(hB0, hB1, hA0, hA1, sW2, sb2, sa2);
    layer2<32>(hA0, hA1, hB0, hB1, sW3, sb3, sa3);

    // Output layer: 32 -> 3 per pixel, tanh
    {
        float o0 = sbo[0], o1 = sbo[1], o2 = sbo[2];
        float q0 = sbo[0], q1 = sbo[1], q2 = sbo[2];
#pragma unroll
        for (int k = 0; k < 32; k++) {
            float w0 = sWo[3 * k + 0], w1 = sWo[3 * k + 1], w2 = sWo[3 * k + 2];
            o0 = fmaf(hB0[k], w0, o0);
            o1 = fmaf(hB0[k], w1, o1);
            o2 = fmaf(hB0[k], w2, o2);
            q0 = fmaf(hB1[k], w0, q0);
            q1 = fmaf(hB1[k], w1, q1);
            q2 = fmaf(hB1[k], w2, q2);
        }
        out[3 * p0 + 0] = fast_tanh(o0);
        out[3 * p0 + 1] = fast_tanh(o1);
        out[3 * p0 + 2] = fast_tanh(o2);
        if (has1) {
            out[3 * p1 + 0] = fast_tanh(q0);
            out[3 * p1 + 1] = fast_tanh(q1);
            out[3 * p1 + 2] = fast_tanh(q2);
        }
    }
}

extern "C" void kernel_launch(void* const* d_in, const int* in_sizes, int n_in,
                              void* d_out, int out_size) {
    const float* inp  = (const float*)d_in[0];
    const float* bin  = (const float*)d_in[1];
    const float* W1   = (const float*)d_in[2];
    const float* b1   = (const float*)d_in[3];
    const int*   a1   = (const int*)  d_in[4];
    const float* W2   = (const float*)d_in[5];
    const float* b2   = (const float*)d_in[6];
    const int*   a2   = (const int*)  d_in[7];
    const float* W3   = (const float*)d_in[8];
    const float* b3   = (const float*)d_in[9];
    const int*   a3   = (const int*)  d_in[10];
    const float* Wo   = (const float*)d_in[11];
    const float* bo   = (const float*)d_in[12];
    float* out = (float*)d_out;

    const int P = in_sizes[0] / 12;
    const int blocks = (P + 255) / 256;   // 2 pixels per thread
    cppn_kernel<<<blocks, 128>>>(inp, bin, W1, b1, a1, W2, b2, a2,
                                 W3, b3, a3, Wo, bo, out, P);
}

// round 7
// speedup vs baseline: 2.2297x; 2.2297x over previous
#include <cuda_runtime.h>

// CPPN: [P,12] -> 32 -> 32 -> 32 -> 3, per-node activations, tanh output.
// R6 resubmit: R5 architecture with the sW1 staging bug fixed (strided loop,
// 384 elems > 256 threads). 1 px/thread; layer as 2 half-passes (16 outs)
// so only 8 u64 accumulators are live -> ~110-128 regs at launch_bounds(256,2)
// -> 16 warps/SM, no spills. ulonglong2 weight loads: LDS.128 register pairs
// ARE the f32x2 operands. FFMA2 everywhere.

typedef unsigned long long ull;

__device__ __forceinline__ ull dup2(float x) {
    ull r; asm("mov.b64 %0, {%1, %2};" : "=l"(r) : "f"(x), "f"(x)); return r;
}
__device__ __forceinline__ ull ffma2(ull a, ull b, ull c) {
    ull d; asm("fma.rn.f32x2 %0, %1, %2, %3;" : "=l"(d) : "l"(a), "l"(b), "l"(c)); return d;
}
__device__ __forceinline__ void unpk2(ull v, float& lo, float& hi) {
    asm("mov.b64 {%0, %1}, %2;" : "=f"(lo), "=f"(hi) : "l"(v));
}

// Overflow-safe fast tanh: tanh(x) = sign(x)*(1-e)/(1+e), e = exp(-2|x|) <= 1
__device__ __forceinline__ float fast_tanh(float x) {
    float ax = fabsf(x);
    float e  = __expf(-2.0f * ax);
    float t  = __fdividef(1.0f - e, 1.0f + e);
    return copysignf(t, x);
}

// 0=identity, 1=tanh, 2=sigmoid, 3=sin, 4=gaussian
__device__ __forceinline__ float actf(float x, int id) {
    switch (id) {
        case 1:  return fast_tanh(x);
        case 2:  return __fdividef(1.0f, 1.0f + __expf(-x));
        case 3:  return __sinf(x);
        case 4:  return __expf(-0.5f * x * x);
        default: return x;
    }
}

// One hidden layer, K inputs -> 32 outputs, h in/out as plain f32[32].
// Two half-passes of 16 outputs so only 8 u64 accumulators are live at once.
template <int K>
__device__ __forceinline__ void layer1(const float* __restrict__ h,
                                       float* __restrict__ o,
                                       const float* __restrict__ sW,
                                       const float* __restrict__ sb,
                                       const int* __restrict__ sact) {
#pragma unroll
    for (int half = 0; half < 2; half++) {
        const int jb = 16 * half;
        ull acc[8];
#pragma unroll
        for (int j = 0; j < 8; j++)
            acc[j] = *(const ull*)(sb + jb + 2 * j);
#pragma unroll
        for (int k = 0; k < K; k++) {
            ull hk = dup2(h[k]);
            const ulonglong2* wrow = (const ulonglong2*)(sW + k * 32 + jb);
#pragma unroll
            for (int jq = 0; jq < 4; jq++) {
                ulonglong2 w = wrow[jq];          // LDS.128 -> two f32x2 operands
                acc[2 * jq + 0] = ffma2(hk, w.x, acc[2 * jq + 0]);
                acc[2 * jq + 1] = ffma2(hk, w.y, acc[2 * jq + 1]);
            }
        }
#pragma unroll
        for (int j = 0; j < 8; j++) {
            float x0, x1;
            unpk2(acc[j], x0, x1);
            o[jb + 2 * j + 0] = actf(x0, sact[jb + 2 * j + 0]);
            o[jb + 2 * j + 1] = actf(x1, sact[jb + 2 * j + 1]);
        }
    }
}

__global__ __launch_bounds__(256, 2) void cppn_kernel(
    const float* __restrict__ inp,       // [P,12]
    const float* __restrict__ bias_in,   // [12]
    const float* __restrict__ W1,        // [12,32]
    const float* __restrict__ b1,        // [32]
    const int*   __restrict__ a1,        // [32]
    const float* __restrict__ W2,        // [32,32]
    const float* __restrict__ b2,
    const int*   __restrict__ a2,
    const float* __restrict__ W3,        // [32,32]
    const float* __restrict__ b3,
    const int*   __restrict__ a3,
    const float* __restrict__ Wo,        // [32,3]
    const float* __restrict__ bo,        // [3]
    float* __restrict__ out,             // [P,3]
    int P)
{
    __shared__ __align__(16) float sW1[12 * 32];
    __shared__ __align__(16) float sW2[32 * 32];
    __shared__ __align__(16) float sW3[32 * 32];
    __shared__ __align__(16) float sWo[96];
    __shared__ __align__(16) float sb1[32], sb2[32], sb3[32];
    __shared__ float sbo[3], sbin[12];
    __shared__ int   sa1[32], sa2[32], sa3[32];

    const int t = threadIdx.x;
    for (int i = t; i < 12 * 32; i += 256) sW1[i] = W1[i];   // 384 elems: strided!
    for (int i = t; i < 1024; i += 256) { sW2[i] = W2[i]; sW3[i] = W3[i]; }
    if (t < 96) sWo[t] = Wo[t];
    if (t < 32) {
        sb1[t] = b1[t]; sb2[t] = b2[t]; sb3[t] = b3[t];
        sa1[t] = a1[t]; sa2[t] = a2[t]; sa3[t] = a3[t];
    }
    if (t < 12) sbin[t] = bias_in[t];
    if (t < 3)  sbo[t]  = bo[t];
    __syncthreads();

    const int p = blockIdx.x * 256 + t;
    if (p >= P) return;

    // Load 12 inputs as 3x float4 (rows are 48B, 16B-aligned)
    const float4* in4 = (const float4*)inp;
    float4 A = in4[3 * p + 0];
    float4 B = in4[3 * p + 1];
    float4 C = in4[3 * p + 2];

    float hA[32], hB[32];
    hA[0]  = A.x + sbin[0];  hA[1]  = A.y + sbin[1];
    hA[2]  = A.z + sbin[2];  hA[3]  = A.w + sbin[3];
    hA[4]  = B.x + sbin[4];  hA[5]  = B.y + sbin[5];
    hA[6]  = B.z + sbin[6];  hA[7]  = B.w + sbin[7];
    hA[8]  = C.x + sbin[8];  hA[9]  = C.y + sbin[9];
    hA[10] = C.z + sbin[10]; hA[11] = C.w + sbin[11];

    layer1<12>(hA, hB, sW1, sb1, sa1);
    layer1<32>(hB, hA, sW2, sb2, sa2);
    layer1<32>(hA, hB, sW3, sb3, sa3);

    // Output layer: 32 -> 3, then tanh
    float o0 = sbo[0], o1 = sbo[1], o2 = sbo[2];
#pragma unroll
    for (int k = 0; k < 32; k++) {
        float hk = hB[k];
        o0 = fmaf(hk, sWo[3 * k + 0], o0);
        o1 = fmaf(hk, sWo[3 * k + 1], o1);
        o2 = fmaf(hk, sWo[3 * k + 2], o2);
    }
    out[3 * p + 0] = fast_tanh(o0);
    out[3 * p + 1] = fast_tanh(o1);
    out[3 * p + 2] = fast_tanh(o2);
}

extern "C" void kernel_launch(void* const* d_in, const int* in_sizes, int n_in,
                              void* d_out, int out_size) {
    const float* inp  = (const float*)d_in[0];
    const float* bin  = (const float*)d_in[1];
    const float* W1   = (const float*)d_in[2];
    const float* b1   = (const float*)d_in[3];
    const int*   a1   = (const int*)  d_in[4];
    const float* W2   = (const float*)d_in[5];
    const float* b2   = (const float*)d_in[6];
    const int*   a2   = (const int*)  d_in[7];
    const float* W3   = (const float*)d_in[8];
    const float* b3   = (const float*)d_in[9];
    const int*   a3   = (const int*)  d_in[10];
    const float* Wo   = (const float*)d_in[11];
    const float* bo   = (const float*)d_in[12];
    float* out = (float*)d_out;

    const int P = in_sizes[0] / 12;
    const int blocks = (P + 255) / 256;
    cppn_kernel<<<blocks, 256>>>(inp, bin, W1, b1, a1, W2, b2, a2,
                                 W3, b3, a3, Wo, bo, out, P);
}

// round 13
// speedup vs baseline: 2.3971x; 1.0750x over previous
#include <cuda_runtime.h>

// CPPN: [P,12] -> 32 -> 32 -> 32 -> 3, per-node activations, tanh output.
// R8 resubmit (x5): occupancy is king (20w=195us, 16w=225us, 8w=502us).
// Quarter-pass layers (8 outputs per pass, 4 u64 accs live) shrink peak live
// state to ~80 regs so __launch_bounds__(128,6) -> 24 warps/SM with no spills.
// ulonglong2 weight loads: LDS.128 register pairs ARE the f32x2 operands.
// FFMA2 everywhere.

typedef unsigned long long ull;

__device__ __forceinline__ ull dup2(float x) {
    ull r; asm("mov.b64 %0, {%1, %2};" : "=l"(r) : "f"(x), "f"(x)); return r;
}
__device__ __forceinline__ ull ffma2(ull a, ull b, ull c) {
    ull d; asm("fma.rn.f32x2 %0, %1, %2, %3;" : "=l"(d) : "l"(a), "l"(b), "l"(c)); return d;
}
__device__ __forceinline__ void unpk2(ull v, float& lo, float& hi) {
    asm("mov.b64 {%0, %1}, %2;" : "=f"(lo), "=f"(hi) : "l"(v));
}

// Overflow-safe fast tanh: tanh(x) = sign(x)*(1-e)/(1+e), e = exp(-2|x|) <= 1
__device__ __forceinline__ float fast_tanh(float x) {
    float ax = fabsf(x);
    float e  = __expf(-2.0f * ax);
    float t  = __fdividef(1.0f - e, 1.0f + e);
    return copysignf(t, x);
}

// 0=identity, 1=tanh, 2=sigmoid, 3=sin, 4=gaussian
// act ids are per-node (uniform across lanes) -> branches are warp-uniform.
__device__ __forceinline__ float actf(float x, int id) {
    switch (id) {
        case 1:  return fast_tanh(x);
        case 2:  return __fdividef(1.0f, 1.0f + __expf(-x));
        case 3:  return __sinf(x);
        case 4:  return __expf(-0.5f * x * x);
        default: return x;
    }
}

// One hidden layer, K inputs -> 32 outputs, h in/out plain f32[32].
// Four quarter-passes of 8 outputs: only 4 u64 accumulators live at once.
template <int K>
__device__ __forceinline__ void layer1(const float* __restrict__ h,
                                       float* __restrict__ o,
                                       const float* __restrict__ sW,
                                       const float* __restrict__ sb,
                                       const int* __restrict__ sact) {
#pragma unroll
    for (int q = 0; q < 4; q++) {
        const int jb = 8 * q;
        ull acc[4];
#pragma unroll
        for (int j = 0; j < 4; j++)
            acc[j] = *(const ull*)(sb + jb + 2 * j);
#pragma unroll
        for (int k = 0; k < K; k++) {
            ull hk = dup2(h[k]);
            const ulonglong2* wrow = (const ulonglong2*)(sW + k * 32 + jb);
            ulonglong2 w0 = wrow[0];              // LDS.128 -> two f32x2 operands
            ulonglong2 w1 = wrow[1];
            acc[0] = ffma2(hk, w0.x, acc[0]);
            acc[1] = ffma2(hk, w0.y, acc[1]);
            acc[2] = ffma2(hk, w1.x, acc[2]);
            acc[3] = ffma2(hk, w1.y, acc[3]);
        }
#pragma unroll
        for (int j = 0; j < 4; j++) {
            float x0, x1;
            unpk2(acc[j], x0, x1);
            o[jb + 2 * j + 0] = actf(x0, sact[jb + 2 * j + 0]);
            o[jb + 2 * j + 1] = actf(x1, sact[jb + 2 * j + 1]);
        }
    }
}

__global__ __launch_bounds__(128, 6) void cppn_kernel(
    const float* __restrict__ inp,       // [P,12]
    const float* __restrict__ bias_in,   // [12]
    const float* __restrict__ W1,        // [12,32]
    const float* __restrict__ b1,        // [32]
    const int*   __restrict__ a1,        // [32]
    const float* __restrict__ W2,        // [32,32]
    const float* __restrict__ b2,
    const int*   __restrict__ a2,
    const float* __restrict__ W3,        // [32,32]
    const float* __restrict__ b3,
    const int*   __restrict__ a3,
    const float* __restrict__ Wo,        // [32,3]
    const float* __restrict__ bo,        // [3]
    float* __restrict__ out,             // [P,3]
    int P)
{
    __shared__ __align__(16) float sW1[12 * 32];
    __shared__ __align__(16) float sW2[32 * 32];
    __shared__ __align__(16) float sW3[32 * 32];
    __shared__ __align__(16) float sWo[96];
    __shared__ __align__(16) float sb1[32], sb2[32], sb3[32];
    __shared__ float sbo[3], sbin[12];
    __shared__ int   sa1[32], sa2[32], sa3[32];

    const int t = threadIdx.x;
    for (int i = t; i < 12 * 32; i += 128) sW1[i] = W1[i];
    for (int i = t; i < 1024; i += 128) { sW2[i] = W2[i]; sW3[i] = W3[i]; }
    if (t < 96) sWo[t] = Wo[t];
    if (t < 32) {
        sb1[t] = b1[t]; sb2[t] = b2[t]; sb3[t] = b3[t];
        sa1[t] = a1[t]; sa2[t] = a2[t]; sa3[t] = a3[t];
    }
    if (t < 12) sbin[t] = bias_in[t];
    if (t < 3)  sbo[t]  = bo[t];
    __syncthreads();

    const int p = blockIdx.x * 128 + t;
    if (p >= P) return;

    // Load 12 inputs as 3x float4 (rows are 48B, 16B-aligned)
    const float4* in4 = (const float4*)inp;
    float4 A = in4[3 * p + 0];
    float4 B = in4[3 * p + 1];
    float4 C = in4[3 * p + 2];

    float hA[32], hB[32];
    hA[0]  = A.x + sbin[0];  hA[1]  = A.y + sbin[1];
    hA[2]  = A.z + sbin[2];  hA[3]  = A.w + sbin[3];
    hA[4]  = B.x + sbin[4];  hA[5]  = B.y + sbin[5];
    hA[6]  = B.z + sbin[6];  hA[7]  = B.w + sbin[7];
    hA[8]  = C.x + sbin[8];  hA[9]  = C.y + sbin[9];
    hA[10] = C.z + sbin[10]; hA[11] = C.w + sbin[11];

    layer1<12>(hA, hB, sW1, sb1, sa1);
    layer1<32>(hB, hA, sW2, sb2, sa2);
    layer1<32>(hA, hB, sW3, sb3, sa3);

    // Output layer: 32 -> 3, then tanh
    float o0 = sbo[0], o1 = sbo[1], o2 = sbo[2];
#pragma unroll
    for (int k = 0; k < 32; k++) {
        float hk = hB[k];
        o0 = fmaf(hk, sWo[3 * k + 0], o0);
        o1 = fmaf(hk, sWo[3 * k + 1], o1);
        o2 = fmaf(hk, sWo[3 * k + 2], o2);
    }
    out[3 * p + 0] = fast_tanh(o0);
    out[3 * p + 1] = fast_tanh(o1);
    out[3 * p + 2] = fast_tanh(o2);
}

extern "C" void kernel_launch(void* const* d_in, const int* in_sizes, int n_in,
                              void* d_out, int out_size) {
    const float* inp  = (const float*)d_in[0];
    const float* bin  = (const float*)d_in[1];
    const float* W1   = (const float*)d_in[2];
    const float* b1   = (const float*)d_in[3];
    const int*   a1   = (const int*)  d_in[4];
    const float* W2   = (const float*)d_in[5];
    const float* b2   = (const float*)d_in[6];
    const int*   a2   = (const int*)  d_in[7];
    const float* W3   = (const float*)d_in[8];
    const float* b3   = (const float*)d_in[9];
    const int*   a3   = (const int*)  d_in[10];
    const float* Wo   = (const float*)d_in[11];
    const float* bo   = (const float*)d_in[12];
    float* out = (float*)d_out;

    const int P = in_sizes[0] / 12;
    const int blocks = (P + 127) / 128;
    cppn_kernel<<<blocks, 128>>>(inp, bin, W1, b1, a1, W2, b2, a2,
                                 W3, b3, a3, Wo, bo, out, P);
}